// round 9
// baseline (speedup 1.0000x reference)
#include <cuda_runtime.h>
#include <cuda_bf16.h>
#include <cstdint>

#define DMODEL 1024
#define DIN    2048
#define DSTATE 16
#define DCONV  4
#define DTRANK 64
#define BSZ    2
#define LSEQ   2048
#define MTOT   (BSZ*LSEQ)            // 4096 rows
#define NXP    (DTRANK + 2*DSTATE)   // 96

// ---------------- scratch (static device globals; no allocation) ----------------
__device__ float g_xz[(size_t)MTOT * 2 * DIN];
__device__ float g_xdbl_part[4ull * MTOT * NXP];
__device__ float g_xdbl[(size_t)MTOT * NXP];
__device__ float g_dt[(size_t)MTOT * DIN];
__device__ float g_mo[(size_t)MTOT * DMODEL];

// bf16 hi/lo operand buffers
__device__ __nv_bfloat16 g_xhi[(size_t)MTOT * DMODEL];
__device__ __nv_bfloat16 g_xlo[(size_t)MTOT * DMODEL];
__device__ __nv_bfloat16 g_wihi[(size_t)2 * DIN * DMODEL];
__device__ __nv_bfloat16 g_wilo[(size_t)2 * DIN * DMODEL];
__device__ __nv_bfloat16 g_wohi[(size_t)DMODEL * DIN];
__device__ __nv_bfloat16 g_wolo[(size_t)DMODEL * DIN];
__device__ __nv_bfloat16 g_yhi[(size_t)MTOT * DIN];
__device__ __nv_bfloat16 g_ylo[(size_t)MTOT * DIN];
__device__ __nv_bfloat16 g_uchi[(size_t)MTOT * DIN];
__device__ __nv_bfloat16 g_uclo[(size_t)MTOT * DIN];
__device__ __nv_bfloat16 g_xdhi[(size_t)MTOT * NXP];
__device__ __nv_bfloat16 g_xdlo[(size_t)MTOT * NXP];
__device__ __nv_bfloat16 g_wxphi[(size_t)NXP * DIN];
__device__ __nv_bfloat16 g_wxplo[(size_t)NXP * DIN];
__device__ __nv_bfloat16 g_wdthi[(size_t)DIN * DTRANK];
__device__ __nv_bfloat16 g_wdtlo[(size_t)DIN * DTRANK];

// ---------------- cp.async helpers ----------------
__device__ __forceinline__ void cpa4(void* dst, const void* src) {
    uint32_t d = (uint32_t)__cvta_generic_to_shared(dst);
    asm volatile("cp.async.ca.shared.global [%0], [%1], 4;\n" :: "r"(d), "l"(src));
}
__device__ __forceinline__ void cpa8(void* dst, const void* src) {
    uint32_t d = (uint32_t)__cvta_generic_to_shared(dst);
    asm volatile("cp.async.ca.shared.global [%0], [%1], 8;\n" :: "r"(d), "l"(src));
}
__device__ __forceinline__ void cpa16(void* dst, const void* src) {
    uint32_t d = (uint32_t)__cvta_generic_to_shared(dst);
    asm volatile("cp.async.cg.shared.global [%0], [%1], 16;\n" :: "r"(d), "l"(src));
}
__device__ __forceinline__ void cpa16s(uint32_t d, const void* src) {
    asm volatile("cp.async.cg.shared.global [%0], [%1], 16;\n" :: "r"(d), "l"(src));
}
__device__ __forceinline__ void cpa16z(uint32_t d, const void* src) {
    asm volatile("cp.async.cg.shared.global [%0], [%1], 16, 0;\n" :: "r"(d), "l"(src));
}
__device__ __forceinline__ void cp_commit() {
    asm volatile("cp.async.commit_group;\n");
}
template<int N>
__device__ __forceinline__ void cp_wait() {
    asm volatile("cp.async.wait_group %0;\n" :: "n"(N));
}

// ---------------- mma.sync helpers ----------------
__device__ __forceinline__ void ldsm4(uint32_t* r, uint32_t addr) {
    asm volatile("ldmatrix.sync.aligned.m8n8.x4.shared.b16 {%0,%1,%2,%3}, [%4];"
        : "=r"(r[0]), "=r"(r[1]), "=r"(r[2]), "=r"(r[3]) : "r"(addr));
}
__device__ __forceinline__ void mma16816(float* c, const uint32_t* a, const uint32_t* b) {
    asm volatile(
        "mma.sync.aligned.m16n8k16.row.col.f32.bf16.bf16.f32 "
        "{%0,%1,%2,%3}, {%4,%5,%6,%7}, {%8,%9}, {%0,%1,%2,%3};\n"
        : "+f"(c[0]), "+f"(c[1]), "+f"(c[2]), "+f"(c[3])
        : "r"(a[0]), "r"(a[1]), "r"(a[2]), "r"(a[3]), "r"(b[0]), "r"(b[1]));
}

// swizzled smem byte offset for (row, 16B-chunk) in a [rows x 64B] tile
__device__ __forceinline__ uint32_t swz(int row, int c) {
    return (uint32_t)(row * 64 + ((c ^ ((row >> 1) & 3)) << 4));
}

// =============== HMMA GEMM (128x128 tile) for small GEMMs =================
#define HM_STAGE 32768
#define HM_NST   3
#define HM_SMEM  (HM_NST * HM_STAGE + 1024)

template<int EPI>
__global__ __launch_bounds__(256, 1)
void hmma_gemm(const __nv_bfloat16* __restrict__ Ahi, const __nv_bfloat16* __restrict__ Alo,
               const __nv_bfloat16* __restrict__ Bhi, const __nv_bfloat16* __restrict__ Blo,
               float* __restrict__ C, const float* __restrict__ bias,
               int M, int Nb, int K, int lda, int ldb, int ldc)
{
    extern __shared__ uint8_t smem_raw[];
    uint8_t* smem = (uint8_t*)(((uintptr_t)smem_raw + 1023) & ~(uintptr_t)1023);
    const uint32_t sbase = (uint32_t)__cvta_generic_to_shared(smem);

    const int tid = threadIdx.x, wid = tid >> 5, lane = tid & 31;
    const int warp_m = wid & 1, warp_n = wid >> 1;
    const int row0 = blockIdx.y * 128, col0 = blockIdx.x * 128;

    int kRange = K, k0 = 0;
    if (gridDim.z > 1) {
        kRange = K / gridDim.z;
        k0     = blockIdx.z * kRange;
        C     += (size_t)blockIdx.z * M * ldc;
    }
    const int T = kRange >> 5;

    const int t2 = tid >> 6, tl = tid & 63;
    const int cc = tl & 3;
    const int rb = tl >> 2;
    const __nv_bfloat16* gsrc; int roff, ld;
    if      (t2 == 0) { gsrc = Ahi; roff = row0; ld = lda; }
    else if (t2 == 1) { gsrc = Alo; roff = row0; ld = lda; }
    else if (t2 == 2) { gsrc = Bhi; roff = col0; ld = ldb; }
    else              { gsrc = Blo; roff = col0; ld = ldb; }
    const int rowlim = (t2 >= 2) ? Nb : M;
    const uint32_t dsw = (uint32_t)(t2 * 8192) + (uint32_t)rb * 64 +
                         ((uint32_t)(cc ^ ((rb >> 1) & 3)) << 4);
    const uint8_t* gbase = (const uint8_t*)(gsrc + (size_t)(roff + rb) * ld + k0 + cc * 8);
    const size_t grs = (size_t)16 * ld * 2;

    auto load_stage = [&](int tile, int stg) {
        const uint8_t* g = gbase + (size_t)tile * 64;
        uint32_t d = sbase + (uint32_t)stg * HM_STAGE + dsw;
#pragma unroll
        for (int j = 0; j < 8; j++) {
            if (roff + rb + j * 16 < rowlim) cpa16s(d + j * 1024, g + (size_t)j * grs);
            else                             cpa16z(d + j * 1024, g);
        }
    };

    float acc[4][4][4];
#pragma unroll
    for (int i = 0; i < 4; i++)
#pragma unroll
        for (int j = 0; j < 4; j++)
#pragma unroll
            for (int q = 0; q < 4; q++) acc[i][j][q] = 0.f;

    const int aml = lane & 15;
    const int acs = lane >> 4;
    const int bnl = ((lane >> 4) & 1) * 8 + (lane & 7);
    const int bcs = (lane >> 3) & 1;

    for (int s = 0; s < HM_NST && s < T; s++) { load_stage(s, s); cp_commit(); }

    for (int i = 0; i < T; i++) {
        if (i + HM_NST <= T) cp_wait<HM_NST - 1>(); else cp_wait<0>();
        __syncthreads();
        const uint32_t st = sbase + (uint32_t)(i % HM_NST) * HM_STAGE;

#pragma unroll
        for (int s = 0; s < 2; s++) {
            uint32_t ah[4][4], al[4][4], bh[4][2], bl[4][2];
#pragma unroll
            for (int t = 0; t < 4; t++) {
                int m = warp_m * 64 + t * 16 + aml;
                uint32_t off = swz(m, 2 * s + acs);
                ldsm4(ah[t], st + off);
                ldsm4(al[t], st + 8192 + off);
            }
#pragma unroll
            for (int p = 0; p < 2; p++) {
                int n = warp_n * 32 + p * 16 + bnl;
                uint32_t off = swz(n, 2 * s + bcs);
                uint32_t r[4];
                ldsm4(r, st + 16384 + off);
                bh[2*p][0] = r[0]; bh[2*p][1] = r[1];
                bh[2*p+1][0] = r[2]; bh[2*p+1][1] = r[3];
                ldsm4(r, st + 24576 + off);
                bl[2*p][0] = r[0]; bl[2*p][1] = r[1];
                bl[2*p+1][0] = r[2]; bl[2*p+1][1] = r[3];
            }
#pragma unroll
            for (int t = 0; t < 4; t++)
#pragma unroll
                for (int j = 0; j < 4; j++) {
                    mma16816(acc[t][j], ah[t], bh[j]);
                    mma16816(acc[t][j], ah[t], bl[j]);
                    mma16816(acc[t][j], al[t], bh[j]);
                }
        }
        __syncthreads();
        if (i + HM_NST < T) { load_stage(i + HM_NST, i % HM_NST); cp_commit(); }
    }

#pragma unroll
    for (int t = 0; t < 4; t++) {
        int m = row0 + warp_m * 64 + t * 16 + (lane >> 2);
#pragma unroll
        for (int j = 0; j < 4; j++) {
            int n = col0 + warp_n * 32 + j * 8 + (lane & 3) * 2;
            if (n >= Nb) continue;
            float v0 = acc[t][j][0], v1 = acc[t][j][1];
            float v2 = acc[t][j][2], v3 = acc[t][j][3];
            if (EPI == 1) {
                float b0 = bias[n], b1 = bias[n + 1];
                v0 += b0; v1 += b1; v2 += b0; v3 += b1;
                v0 = (v0 > 20.f) ? v0 : log1pf(__expf(v0));
                v1 = (v1 > 20.f) ? v1 : log1pf(__expf(v1));
                v2 = (v2 > 20.f) ? v2 : log1pf(__expf(v2));
                v3 = (v3 > 20.f) ? v3 : log1pf(__expf(v3));
            }
            *(float2*)(C + (size_t)m * ldc + n) = make_float2(v0, v1);
            *(float2*)(C + (size_t)(m + 8) * ldc + n) = make_float2(v2, v3);
        }
    }
}

// =============== HMMA GEMM wide (128x256 tile, warp 64x64) for big GEMMs ==========
#define HW_STAGE 49152            // Ahi 8K | Alo 8K | Bhi 16K | Blo 16K
#define HW_NST   3
#define HW_SMEM  (HW_NST * HW_STAGE + 1024)

__global__ __launch_bounds__(256, 1)
void hmma_gemm_w(const __nv_bfloat16* __restrict__ Ahi, const __nv_bfloat16* __restrict__ Alo,
                 const __nv_bfloat16* __restrict__ Bhi, const __nv_bfloat16* __restrict__ Blo,
                 float* __restrict__ C, int M, int Nb, int K, int lda, int ldb, int ldc)
{
    extern __shared__ uint8_t smem_raw[];
    uint8_t* smem = (uint8_t*)(((uintptr_t)smem_raw + 1023) & ~(uintptr_t)1023);
    const uint32_t sbase = (uint32_t)__cvta_generic_to_shared(smem);

    const int tid = threadIdx.x, wid = tid >> 5, lane = tid & 31;
    const int warp_m = wid & 1, warp_n = wid >> 1;       // 2 x 4, warp tile 64x64
    const int row0 = blockIdx.y * 128, col0 = blockIdx.x * 256;
    const int T = K >> 5;

    const int t2 = tid >> 6, tl = tid & 63;
    const int cc = tl & 3;
    const int rb = tl >> 2;
    const __nv_bfloat16* gsrc; int roff, ld;
    uint32_t tbase;
    if      (t2 == 0) { gsrc = Ahi; roff = row0; ld = lda; tbase = 0; }
    else if (t2 == 1) { gsrc = Alo; roff = row0; ld = lda; tbase = 8192; }
    else if (t2 == 2) { gsrc = Bhi; roff = col0; ld = ldb; tbase = 16384; }
    else              { gsrc = Blo; roff = col0; ld = ldb; tbase = 32768; }
    const int rowlim = (t2 >= 2) ? Nb : M;
    const uint32_t dsw = tbase + (uint32_t)rb * 64 +
                         ((uint32_t)(cc ^ ((rb >> 1) & 3)) << 4);
    const uint8_t* gbase = (const uint8_t*)(gsrc + (size_t)(roff + rb) * ld + cc * 8);
    const size_t grs = (size_t)16 * ld * 2;

    auto load_stage = [&](int tile, int stg) {
        const uint8_t* g = gbase + (size_t)tile * 64;
        uint32_t d = sbase + (uint32_t)stg * HW_STAGE + dsw;
        if (t2 < 2) {
#pragma unroll
            for (int j = 0; j < 8; j++) {
                if (roff + rb + j * 16 < rowlim) cpa16s(d + j * 1024, g + (size_t)j * grs);
                else                             cpa16z(d + j * 1024, g);
            }
        } else {
#pragma unroll
            for (int j = 0; j < 16; j++) {
                if (roff + rb + j * 16 < rowlim) cpa16s(d + j * 1024, g + (size_t)j * grs);
                else                             cpa16z(d + j * 1024, g);
            }
        }
    };

    float acc[4][8][4];
#pragma unroll
    for (int i = 0; i < 4; i++)
#pragma unroll
        for (int j = 0; j < 8; j++)
#pragma unroll
            for (int q = 0; q < 4; q++) acc[i][j][q] = 0.f;

    const int aml = lane & 15;
    const int acs = lane >> 4;
    const int bnl = ((lane >> 4) & 1) * 8 + (lane & 7);
    const int bcs = (lane >> 3) & 1;

    for (int s = 0; s < HW_NST && s < T; s++) { load_stage(s, s); cp_commit(); }

    for (int i = 0; i < T; i++) {
        if (i + HW_NST <= T) cp_wait<HW_NST - 1>(); else cp_wait<0>();
        __syncthreads();
        const uint32_t st = sbase + (uint32_t)(i % HW_NST) * HW_STAGE;

#pragma unroll
        for (int s = 0; s < 2; s++) {
            uint32_t ah[4][4], al[4][4], bh[8][2], bl[8][2];
#pragma unroll
            for (int t = 0; t < 4; t++) {
                int m = warp_m * 64 + t * 16 + aml;
                uint32_t off = swz(m, 2 * s + acs);
                ldsm4(ah[t], st + off);
                ldsm4(al[t], st + 8192 + off);
            }
#pragma unroll
            for (int p = 0; p < 4; p++) {
                int n = warp_n * 64 + p * 16 + bnl;
                uint32_t off = swz(n, 2 * s + bcs);
                uint32_t r[4];
                ldsm4(r, st + 16384 + off);
                bh[2*p][0] = r[0]; bh[2*p][1] = r[1];
                bh[2*p+1][0] = r[2]; bh[2*p+1][1] = r[3];
                ldsm4(r, st + 32768 + off);
                bl[2*p][0] = r[0]; bl[2*p][1] = r[1];
                bl[2*p+1][0] = r[2]; bl[2*p+1][1] = r[3];
            }
#pragma unroll
            for (int t = 0; t < 4; t++)
#pragma unroll
                for (int j = 0; j < 8; j++) {
                    mma16816(acc[t][j], ah[t], bh[j]);
                    mma16816(acc[t][j], ah[t], bl[j]);
                    mma16816(acc[t][j], al[t], bh[j]);
                }
        }
        __syncthreads();
        if (i + HW_NST < T) { load_stage(i + HW_NST, i % HW_NST); cp_commit(); }
    }

#pragma unroll
    for (int t = 0; t < 4; t++) {
        int m = row0 + warp_m * 64 + t * 16 + (lane >> 2);
#pragma unroll
        for (int j = 0; j < 8; j++) {
            int n = col0 + warp_n * 64 + j * 8 + (lane & 3) * 2;
            if (n >= Nb) continue;
            *(float2*)(C + (size_t)m * ldc + n) = make_float2(acc[t][j][0], acc[t][j][1]);
            *(float2*)(C + (size_t)(m + 8) * ldc + n) = make_float2(acc[t][j][2], acc[t][j][3]);
        }
    }
}

// ---------------- fp32 -> bf16 hi/lo splits (3 kernels so in_proj GEMM = launch idx 3) --
__device__ __forceinline__ void split1(const float* s, __nv_bfloat16* hi, __nv_bfloat16* lo, int i) {
    float v = s[i];
    __nv_bfloat16 h = __float2bfloat16(v);
    hi[i] = h;
    lo[i] = __float2bfloat16(v - __bfloat162float(h));
}

__global__ void split_x_kernel(const float* __restrict__ x, __nv_bfloat16* __restrict__ xhi,
                               __nv_bfloat16* __restrict__ xlo)
{
    int i = blockIdx.x * blockDim.x + threadIdx.x;
    if (i < MTOT * DMODEL) split1(x, xhi, xlo, i);
}

__global__ void split_win_kernel(const float* __restrict__ w, __nv_bfloat16* __restrict__ whi,
                                 __nv_bfloat16* __restrict__ wlo)
{
    int i = blockIdx.x * blockDim.x + threadIdx.x;
    if (i < 2 * DIN * DMODEL) split1(w, whi, wlo, i);
}

__global__ void split_wrest_kernel(const float* __restrict__ wxp, __nv_bfloat16* __restrict__ xph,
                                   __nv_bfloat16* __restrict__ xpl,
                                   const float* __restrict__ wdt, __nv_bfloat16* __restrict__ dth,
                                   __nv_bfloat16* __restrict__ dtl,
                                   const float* __restrict__ wo, __nv_bfloat16* __restrict__ woh,
                                   __nv_bfloat16* __restrict__ wol)
{
    const int n1 = NXP * DIN, n2 = DIN * DTRANK, n3 = DMODEL * DIN;
    int i = blockIdx.x * blockDim.x + threadIdx.x;
    if (i < n1) split1(wxp, xph, xpl, i);
    else if (i < n1 + n2) split1(wdt, dth, dtl, i - n1);
    else if (i < n1 + n2 + n3) split1(wo, woh, wol, i - n1 - n2);
}

// ---------------- split-K reduce (4 partials) + bf16 hi/lo emit ----------------
__global__ void reduce4_emit(const float* __restrict__ part, float* __restrict__ o,
                             __nv_bfloat16* __restrict__ ohi, __nv_bfloat16* __restrict__ olo,
                             int n)
{
    int i = blockIdx.x * blockDim.x + threadIdx.x;
    if (i < n) {
        float s = part[i] + part[(size_t)n + i] + part[2ull * n + i] + part[3ull * n + i];
        o[i] = s;
        __nv_bfloat16 h = __float2bfloat16(s);
        ohi[i] = h;
        olo[i] = __float2bfloat16(s - __bfloat162float(h));
    }
}

// ---------------- depthwise causal conv(4) + bias + SiLU (emits bf16 hi/lo only) ------
__global__ __launch_bounds__(256)
void conv_silu_kernel(const float* __restrict__ xz, const float* __restrict__ cw,
                      const float* __restrict__ cb,
                      __nv_bfloat16* __restrict__ uchi, __nv_bfloat16* __restrict__ uclo)
{
    int idx = blockIdx.x * blockDim.x + threadIdx.x;
    if (idx >= MTOT * DIN / 4) return;
    const int d4  = idx & (DIN / 4 - 1);
    const int row = idx >> 9;
    const int t   = row & (LSEQ - 1);
    const int d   = d4 * 4;
    const int rs  = 2 * DIN;

    const float4* base = (const float4*)(xz + (size_t)row * rs + d);
    float4 x0 = base[0];
    float4 xm1 = (t >= 1) ? *(const float4*)((const float*)base - rs)     : make_float4(0,0,0,0);
    float4 xm2 = (t >= 2) ? *(const float4*)((const float*)base - 2 * rs) : make_float4(0,0,0,0);
    float4 xm3 = (t >= 3) ? *(const float4*)((const float*)base - 3 * rs) : make_float4(0,0,0,0);

    const float4* cw4 = (const float4*)(cw + d * 4);
    float4 w0 = cw4[0], w1 = cw4[1], w2 = cw4[2], w3 = cw4[3];
    float4 bb = *(const float4*)(cb + d);

    float4 a;
    a.x = bb.x + w0.x * xm3.x + w0.y * xm2.x + w0.z * xm1.x + w0.w * x0.x;
    a.y = bb.y + w1.x * xm3.y + w1.y * xm2.y + w1.z * xm1.y + w1.w * x0.y;
    a.z = bb.z + w2.x * xm3.z + w2.y * xm2.z + w2.z * xm1.z + w2.w * x0.z;
    a.w = bb.w + w3.x * xm3.w + w3.y * xm2.w + w3.z * xm1.w + w3.w * x0.w;

    a.x = a.x / (1.f + __expf(-a.x));
    a.y = a.y / (1.f + __expf(-a.y));
    a.z = a.z / (1.f + __expf(-a.z));
    a.w = a.w / (1.f + __expf(-a.w));

    size_t o = (size_t)row * DIN + d;
    __nv_bfloat16 h0 = __float2bfloat16(a.x), h1 = __float2bfloat16(a.y);
    __nv_bfloat16 h2 = __float2bfloat16(a.z), h3 = __float2bfloat16(a.w);
    __nv_bfloat162* ph = (__nv_bfloat162*)(uchi + o);
    ph[0] = __nv_bfloat162(h0, h1); ph[1] = __nv_bfloat162(h2, h3);
    __nv_bfloat162* pl = (__nv_bfloat162*)(uclo + o);
    pl[0] = __nv_bfloat162(__float2bfloat16(a.x - __bfloat162float(h0)),
                           __float2bfloat16(a.y - __bfloat162float(h1)));
    pl[1] = __nv_bfloat162(__float2bfloat16(a.z - __bfloat162float(h2)),
                           __float2bfloat16(a.w - __bfloat162float(h3)));
}

// ---------------- selective scan (u reconstructed from bf16 hi/lo) ----------------
__global__ __launch_bounds__(128)
void scan_kernel(const float* __restrict__ dt,
                 const __nv_bfloat16* __restrict__ uchi, const __nv_bfloat16* __restrict__ uclo,
                 const float* __restrict__ xz, const float* __restrict__ xdbl,
                 const float* __restrict__ A_log, const float* __restrict__ Dp,
                 __nv_bfloat16* __restrict__ yhi, __nv_bfloat16* __restrict__ ylo)
{
    constexpr int CHB = 8, TC = 32;
    __shared__ __align__(16) float s_dt[2][TC][CHB];
    __shared__ __align__(16) __nv_bfloat162 s_uh[2][TC][CHB / 2];
    __shared__ __align__(16) __nv_bfloat162 s_ul[2][TC][CHB / 2];
    __shared__ __align__(16) float s_z [2][TC][CHB];
    __shared__ __align__(16) float s_bc[2][TC][32];
    __shared__ float s_y[TC][CHB];
    __shared__ float s_D[CHB];

    const int tid  = threadIdx.x;
    const int warp = tid >> 5, lane = tid & 31;
    const int n    = lane & 15;
    const int chw  = lane >> 4;
    const int blk  = blockIdx.x;
    const int b     = blk / (DIN / CHB);
    const int dbase = (blk % (DIN / CHB)) * CHB;
    const int cc    = warp * 2 + chw;
    const int d     = dbase + cc;
    const size_t bL0 = (size_t)b * LSEQ;

    const float Acoef = -__expf(A_log[d * DSTATE + n]);
    if (tid < CHB) s_D[tid] = Dp[dbase + tid];
    float h = 0.f;

    auto load_chunk = [&](int c, int buf) {
        int t0 = c * TC;
#pragma unroll
        for (int i = 0; i < 2; i++) {
            int idx = tid + i * 128;
            int t = idx >> 3, ch = idx & 7;
            size_t r = bL0 + t0 + t;
            cpa4(&s_dt[buf][t][ch], dt + r * DIN + dbase + ch);
            cpa4(&s_z [buf][t][ch], xz + r * (2 * DIN) + DIN + dbase + ch);
            if ((ch & 1) == 0) {   // one bf16x2 pair per 2 channels
                cpa4(&s_uh[buf][t][ch >> 1], uchi + r * DIN + dbase + ch);
                cpa4(&s_ul[buf][t][ch >> 1], uclo + r * DIN + dbase + ch);
            }
        }
#pragma unroll
        for (int i = 0; i < 2; i++) {
            int f = tid + i * 128;
            int t = f >> 3, j = f & 7;
            cpa16(&s_bc[buf][t][j * 4], xdbl + (bL0 + t0 + t) * NXP + DTRANK + j * 4);
        }
    };

    constexpr int NCH = LSEQ / TC;
    load_chunk(0, 0);
    cp_commit();

    for (int c = 0; c < NCH; c++) {
        int buf = c & 1;
        if (c + 1 < NCH) {
            load_chunk(c + 1, buf ^ 1);
            cp_commit();
            cp_wait<1>();
        } else {
            cp_wait<0>();
        }
        __syncthreads();

#pragma unroll 8
        for (int t = 0; t < TC; t++) {
            float dtv = s_dt[buf][t][cc];
            __nv_bfloat162 uh2 = s_uh[buf][t][cc >> 1];
            __nv_bfloat162 ul2 = s_ul[buf][t][cc >> 1];
            float uv = (cc & 1) ? (__bfloat162float(uh2.y) + __bfloat162float(ul2.y))
                                : (__bfloat162float(uh2.x) + __bfloat162float(ul2.x));
            float bv  = s_bc[buf][t][n];
            float cv  = s_bc[buf][t][16 + n];
            float dA  = __expf(dtv * Acoef);
            h = fmaf(h, dA, dtv * uv * bv);
            float p = h * cv;
            p += __shfl_xor_sync(0xffffffffu, p, 1);
            p += __shfl_xor_sync(0xffffffffu, p, 2);
            p += __shfl_xor_sync(0xffffffffu, p, 4);
            p += __shfl_xor_sync(0xffffffffu, p, 8);
            if (n == 0) s_y[t][cc] = p;
        }
        __syncthreads();

        int t0 = c * TC;
#pragma unroll
        for (int i = 0; i < 2; i++) {
            int idx = tid + i * 128;
            int t = idx >> 3, ch = idx & 7;
            float p  = s_y[t][ch];
            __nv_bfloat162 uh2 = s_uh[buf][t][ch >> 1];
            __nv_bfloat162 ul2 = s_ul[buf][t][ch >> 1];
            float uv = (ch & 1) ? (__bfloat162float(uh2.y) + __bfloat162float(ul2.y))
                                : (__bfloat162float(uh2.x) + __bfloat162float(ul2.x));
            float zv = s_z[buf][t][ch];
            float yv = fmaf(s_D[ch], uv, p);
            yv *= zv / (1.f + __expf(-zv));
            __nv_bfloat16 hb = __float2bfloat16(yv);
            size_t o = (bL0 + t0 + t) * DIN + dbase + ch;
            yhi[o] = hb;
            ylo[o] = __float2bfloat16(yv - __bfloat162float(hb));
        }
    }
}

// ---------------- residual + LayerNorm ----------------
__global__ __launch_bounds__(128)
void ln_kernel(const float* __restrict__ mo, const float* __restrict__ x,
               const float* __restrict__ w, const float* __restrict__ bb,
               float* __restrict__ out)
{
    const int row = blockIdx.x, tid = threadIdx.x;
    const float4* m4 = (const float4*)(mo + (size_t)row * DMODEL);
    const float4* x4 = (const float4*)(x  + (size_t)row * DMODEL);

    float4 a0 = m4[tid],       c0 = x4[tid];
    float4 a1 = m4[tid + 128], c1 = x4[tid + 128];
    float4 v0 = make_float4(a0.x + c0.x, a0.y + c0.y, a0.z + c0.z, a0.w + c0.w);
    float4 v1 = make_float4(a1.x + c1.x, a1.y + c1.y, a1.z + c1.z, a1.w + c1.w);

    float s  = v0.x + v0.y + v0.z + v0.w + v1.x + v1.y + v1.z + v1.w;
    float ss = v0.x * v0.x + v0.y * v0.y + v0.z * v0.z + v0.w * v0.w
             + v1.x * v1.x + v1.y * v1.y + v1.z * v1.z + v1.w * v1.w;
#pragma unroll
    for (int m = 16; m; m >>= 1) {
        s  += __shfl_xor_sync(0xffffffffu, s,  m);
        ss += __shfl_xor_sync(0xffffffffu, ss, m);
    }
    __shared__ float rs[4], rss[4];
    if ((tid & 31) == 0) { rs[tid >> 5] = s; rss[tid >> 5] = ss; }
    __syncthreads();
    s  = rs[0]  + rs[1]  + rs[2]  + rs[3];
    ss = rss[0] + rss[1] + rss[2] + rss[3];

    const float mu   = s * (1.f / DMODEL);
    const float var  = ss * (1.f / DMODEL) - mu * mu;
    const float rstd = rsqrtf(var + 1e-5f);

    const float4* w4 = (const float4*)w;
    const float4* b4 = (const float4*)bb;
    float4* o4 = (float4*)(out + (size_t)row * DMODEL);

    float4 ww = w4[tid], bv = b4[tid];
    o4[tid] = make_float4((v0.x - mu) * rstd * ww.x + bv.x,
                          (v0.y - mu) * rstd * ww.y + bv.y,
                          (v0.z - mu) * rstd * ww.z + bv.z,
                          (v0.w - mu) * rstd * ww.w + bv.w);
    ww = w4[tid + 128]; bv = b4[tid + 128];
    o4[tid + 128] = make_float4((v1.x - mu) * rstd * ww.x + bv.x,
                                (v1.y - mu) * rstd * ww.y + bv.y,
                                (v1.z - mu) * rstd * ww.z + bv.z,
                                (v1.w - mu) * rstd * ww.w + bv.w);
}

// ---------------- launch ----------------
extern "C" void kernel_launch(void* const* d_in, const int* in_sizes, int n_in,
                              void* d_out, int out_size)
{
    const float* x      = (const float*)d_in[0];
    const float* w_in   = (const float*)d_in[1];
    const float* conv_w = (const float*)d_in[2];
    const float* conv_b = (const float*)d_in[3];
    const float* w_xp   = (const float*)d_in[4];
    const float* w_dt   = (const float*)d_in[5];
    const float* b_dt   = (const float*)d_in[6];
    const float* A_log  = (const float*)d_in[7];
    const float* Dvec   = (const float*)d_in[8];
    const float* w_out  = (const float*)d_in[9];
    const float* ln_w   = (const float*)d_in[10];
    const float* ln_b   = (const float*)d_in[11];
    float* out = (float*)d_out;

    float *p_xz, *p_xdp, *p_xd, *p_dt, *p_mo;
    __nv_bfloat16 *p_xhi, *p_xlo, *p_wihi, *p_wilo, *p_wohi, *p_wolo, *p_yhi, *p_ylo;
    __nv_bfloat16 *p_uchi, *p_uclo, *p_xdhi, *p_xdlo, *p_wxph, *p_wxpl, *p_wdth, *p_wdtl;
    cudaGetSymbolAddress((void**)&p_xz,  g_xz);
    cudaGetSymbolAddress((void**)&p_xdp, g_xdbl_part);
    cudaGetSymbolAddress((void**)&p_xd,  g_xdbl);
    cudaGetSymbolAddress((void**)&p_dt,  g_dt);
    cudaGetSymbolAddress((void**)&p_mo,  g_mo);
    cudaGetSymbolAddress((void**)&p_xhi, g_xhi);
    cudaGetSymbolAddress((void**)&p_xlo, g_xlo);
    cudaGetSymbolAddress((void**)&p_wihi, g_wihi);
    cudaGetSymbolAddress((void**)&p_wilo, g_wilo);
    cudaGetSymbolAddress((void**)&p_wohi, g_wohi);
    cudaGetSymbolAddress((void**)&p_wolo, g_wolo);
    cudaGetSymbolAddress((void**)&p_yhi, g_yhi);
    cudaGetSymbolAddress((void**)&p_ylo, g_ylo);
    cudaGetSymbolAddress((void**)&p_uchi, g_uchi);
    cudaGetSymbolAddress((void**)&p_uclo, g_uclo);
    cudaGetSymbolAddress((void**)&p_xdhi, g_xdhi);
    cudaGetSymbolAddress((void**)&p_xdlo, g_xdlo);
    cudaGetSymbolAddress((void**)&p_wxph, g_wxphi);
    cudaGetSymbolAddress((void**)&p_wxpl, g_wxplo);
    cudaGetSymbolAddress((void**)&p_wdth, g_wdthi);
    cudaGetSymbolAddress((void**)&p_wdtl, g_wdtlo);

    cudaFuncSetAttribute(hmma_gemm<0>, cudaFuncAttributeMaxDynamicSharedMemorySize, HM_SMEM);
    cudaFuncSetAttribute(hmma_gemm<1>, cudaFuncAttributeMaxDynamicSharedMemorySize, HM_SMEM);
    cudaFuncSetAttribute(hmma_gemm_w, cudaFuncAttributeMaxDynamicSharedMemorySize, HW_SMEM);

    // [0..2] splits (3 launches so the in_proj GEMM is launch index 3 = profiled slot)
    split_x_kernel<<<(MTOT * DMODEL + 255) / 256, 256>>>(x, p_xhi, p_xlo);
    split_win_kernel<<<(2 * DIN * DMODEL + 255) / 256, 256>>>(w_in, p_wihi, p_wilo);
    {
        int nW = NXP * DIN + DIN * DTRANK + DMODEL * DIN;
        split_wrest_kernel<<<(nW + 255) / 256, 256>>>(w_xp, p_wxph, p_wxpl,
                                                      w_dt, p_wdth, p_wdtl,
                                                      w_out, p_wohi, p_wolo);
    }

    // [3] xz = x @ in_proj_w^T   (4096 x 4096, K=1024) -- wide HMMA  << PROFILED >>
    hmma_gemm_w<<<dim3(16, 32), 256, HW_SMEM>>>(p_xhi, p_xlo, p_wihi, p_wilo, p_xz,
                                                MTOT, 2 * DIN, DMODEL,
                                                DMODEL, DMODEL, 2 * DIN);

    // [4] depthwise causal conv + bias + silu -> u_c (bf16 hi/lo only)
    conv_silu_kernel<<<(MTOT * DIN / 4 + 255) / 256, 256>>>(p_xz, conv_w, conv_b,
                                                            p_uchi, p_uclo);

    // [5] x_dbl = u_c @ x_proj_w^T  (4096 x 96, K=2048), HMMA split-K 4 + reduce
    hmma_gemm<0><<<dim3(1, 32, 4), 256, HM_SMEM>>>(p_uchi, p_uclo, p_wxph, p_wxpl, p_xdp,
                                                   nullptr, MTOT, NXP, DIN,
                                                   DIN, DIN, NXP);
    // [6]
    reduce4_emit<<<(MTOT * NXP + 255) / 256, 256>>>(p_xdp, p_xd, p_xdhi, p_xdlo, MTOT * NXP);

    // [7] dt = softplus(x_dbl[:, :64] @ dt_proj_w^T + b)  (4096 x 2048, K=64)
    hmma_gemm<1><<<dim3(16, 32, 1), 256, HM_SMEM>>>(p_xdhi, p_xdlo, p_wdth, p_wdtl, p_dt,
                                                    b_dt, MTOT, DIN, DTRANK,
                                                    NXP, DTRANK, DIN);

    // [8] selective scan (+ D*u, * silu(z)) -> y (bf16 hi/lo)
    scan_kernel<<<BSZ * DIN / 8, 128>>>(p_dt, p_uchi, p_uclo, p_xz, p_xd, A_log, Dvec,
                                        p_yhi, p_ylo);

    // [9] mo = y @ out_proj_w^T  (4096 x 1024, K=2048) -- wide HMMA
    hmma_gemm_w<<<dim3(4, 32), 256, HW_SMEM>>>(p_yhi, p_ylo, p_wohi, p_wolo, p_mo,
                                               MTOT, DMODEL, DIN,
                                               DIN, DIN, DMODEL);

    // [10] out = LayerNorm(mo + x)
    ln_kernel<<<MTOT, 128>>>(p_mo, x, ln_w, ln_b, out);
}

// round 12
// speedup vs baseline: 1.0813x; 1.0813x over previous
#include <cuda_runtime.h>
#include <cuda_bf16.h>
#include <cstdint>

#define DMODEL 1024
#define DIN    2048
#define DSTATE 16
#define DCONV  4
#define DTRANK 64
#define BSZ    2
#define LSEQ   2048
#define MTOT   (BSZ*LSEQ)            // 4096 rows
#define NXP    (DTRANK + 2*DSTATE)   // 96

// ---------------- scratch (static device globals; no allocation) ----------------
__device__ float g_xz[(size_t)MTOT * 2 * DIN];
__device__ float g_xdbl_part[4ull * MTOT * NXP];
__device__ float g_xdbl[(size_t)MTOT * NXP];
__device__ float g_dt[(size_t)MTOT * DIN];
__device__ float g_mo[(size_t)MTOT * DMODEL];

// bf16 hi/lo operand buffers
__device__ __nv_bfloat16 g_xhi[(size_t)MTOT * DMODEL];
__device__ __nv_bfloat16 g_xlo[(size_t)MTOT * DMODEL];
__device__ __nv_bfloat16 g_wihi[(size_t)2 * DIN * DMODEL];
__device__ __nv_bfloat16 g_wilo[(size_t)2 * DIN * DMODEL];
__device__ __nv_bfloat16 g_wohi[(size_t)DMODEL * DIN];
__device__ __nv_bfloat16 g_wolo[(size_t)DMODEL * DIN];
__device__ __nv_bfloat16 g_yhi[(size_t)MTOT * DIN];
__device__ __nv_bfloat16 g_ylo[(size_t)MTOT * DIN];
__device__ __nv_bfloat16 g_uchi[(size_t)MTOT * DIN];
__device__ __nv_bfloat16 g_uclo[(size_t)MTOT * DIN];
__device__ __nv_bfloat16 g_xdhi[(size_t)MTOT * NXP];
__device__ __nv_bfloat16 g_xdlo[(size_t)MTOT * NXP];
__device__ __nv_bfloat16 g_wxphi[(size_t)NXP * DIN];
__device__ __nv_bfloat16 g_wxplo[(size_t)NXP * DIN];
__device__ __nv_bfloat16 g_wdthi[(size_t)DIN * DTRANK];
__device__ __nv_bfloat16 g_wdtlo[(size_t)DIN * DTRANK];

// ---------------- cp.async helpers ----------------
__device__ __forceinline__ void cpa4(void* dst, const void* src) {
    uint32_t d = (uint32_t)__cvta_generic_to_shared(dst);
    asm volatile("cp.async.ca.shared.global [%0], [%1], 4;\n" :: "r"(d), "l"(src));
}
__device__ __forceinline__ void cpa16(void* dst, const void* src) {
    uint32_t d = (uint32_t)__cvta_generic_to_shared(dst);
    asm volatile("cp.async.cg.shared.global [%0], [%1], 16;\n" :: "r"(d), "l"(src));
}
__device__ __forceinline__ void cpa16s(uint32_t d, const void* src) {
    asm volatile("cp.async.cg.shared.global [%0], [%1], 16;\n" :: "r"(d), "l"(src));
}
__device__ __forceinline__ void cpa16z(uint32_t d, const void* src) {
    asm volatile("cp.async.cg.shared.global [%0], [%1], 16, 0;\n" :: "r"(d), "l"(src));
}
__device__ __forceinline__ void cp_commit() {
    asm volatile("cp.async.commit_group;\n");
}
template<int N>
__device__ __forceinline__ void cp_wait() {
    asm volatile("cp.async.wait_group %0;\n" :: "n"(N));
}

// ---------------- mma.sync helpers ----------------
__device__ __forceinline__ void ldsm4(uint32_t* r, uint32_t addr) {
    asm volatile("ldmatrix.sync.aligned.m8n8.x4.shared.b16 {%0,%1,%2,%3}, [%4];"
        : "=r"(r[0]), "=r"(r[1]), "=r"(r[2]), "=r"(r[3]) : "r"(addr));
}
__device__ __forceinline__ void mma16816(float* c, const uint32_t* a, const uint32_t* b) {
    asm volatile(
        "mma.sync.aligned.m16n8k16.row.col.f32.bf16.bf16.f32 "
        "{%0,%1,%2,%3}, {%4,%5,%6,%7}, {%8,%9}, {%0,%1,%2,%3};\n"
        : "+f"(c[0]), "+f"(c[1]), "+f"(c[2]), "+f"(c[3])
        : "r"(a[0]), "r"(a[1]), "r"(a[2]), "r"(a[3]), "r"(b[0]), "r"(b[1]));
}

// swizzled smem byte offset for (row, 16B-chunk) in a [rows x 64B] tile
__device__ __forceinline__ uint32_t swz(int row, int c) {
    return (uint32_t)(row * 64 + ((c ^ ((row >> 1) & 3)) << 4));
}

// =============== HMMA GEMM (128x128 tile) for small GEMMs =================
#define HM_STAGE 32768
#define HM_NST   3
#define HM_SMEM  (HM_NST * HM_STAGE + 1024)

template<int EPI>
__global__ __launch_bounds__(256, 1)
void hmma_gemm(const __nv_bfloat16* __restrict__ Ahi, const __nv_bfloat16* __restrict__ Alo,
               const __nv_bfloat16* __restrict__ Bhi, const __nv_bfloat16* __restrict__ Blo,
               float* __restrict__ C, const float* __restrict__ bias,
               int M, int Nb, int K, int lda, int ldb, int ldc)
{
    extern __shared__ uint8_t smem_raw[];
    uint8_t* smem = (uint8_t*)(((uintptr_t)smem_raw + 1023) & ~(uintptr_t)1023);
    const uint32_t sbase = (uint32_t)__cvta_generic_to_shared(smem);

    const int tid = threadIdx.x, wid = tid >> 5, lane = tid & 31;
    const int warp_m = wid & 1, warp_n = wid >> 1;
    const int row0 = blockIdx.y * 128, col0 = blockIdx.x * 128;

    int kRange = K, k0 = 0;
    if (gridDim.z > 1) {
        kRange = K / gridDim.z;
        k0     = blockIdx.z * kRange;
        C     += (size_t)blockIdx.z * M * ldc;
    }
    const int T = kRange >> 5;

    const int t2 = tid >> 6, tl = tid & 63;
    const int cc = tl & 3;
    const int rb = tl >> 2;
    const __nv_bfloat16* gsrc; int roff, ld;
    if      (t2 == 0) { gsrc = Ahi; roff = row0; ld = lda; }
    else if (t2 == 1) { gsrc = Alo; roff = row0; ld = lda; }
    else if (t2 == 2) { gsrc = Bhi; roff = col0; ld = ldb; }
    else              { gsrc = Blo; roff = col0; ld = ldb; }
    const int rowlim = (t2 >= 2) ? Nb : M;
    const uint32_t dsw = (uint32_t)(t2 * 8192) + (uint32_t)rb * 64 +
                         ((uint32_t)(cc ^ ((rb >> 1) & 3)) << 4);
    const uint8_t* gbase = (const uint8_t*)(gsrc + (size_t)(roff + rb) * ld + k0 + cc * 8);
    const size_t grs = (size_t)16 * ld * 2;

    auto load_stage = [&](int tile, int stg) {
        const uint8_t* g = gbase + (size_t)tile * 64;
        uint32_t d = sbase + (uint32_t)stg * HM_STAGE + dsw;
#pragma unroll
        for (int j = 0; j < 8; j++) {
            if (roff + rb + j * 16 < rowlim) cpa16s(d + j * 1024, g + (size_t)j * grs);
            else                             cpa16z(d + j * 1024, g);
        }
    };

    float acc[4][4][4];
#pragma unroll
    for (int i = 0; i < 4; i++)
#pragma unroll
        for (int j = 0; j < 4; j++)
#pragma unroll
            for (int q = 0; q < 4; q++) acc[i][j][q] = 0.f;

    const int aml = lane & 15;
    const int acs = lane >> 4;
    const int bnl = ((lane >> 4) & 1) * 8 + (lane & 7);
    const int bcs = (lane >> 3) & 1;

    for (int s = 0; s < HM_NST && s < T; s++) { load_stage(s, s); cp_commit(); }

    for (int i = 0; i < T; i++) {
        if (i + HM_NST <= T) cp_wait<HM_NST - 1>(); else cp_wait<0>();
        __syncthreads();
        const uint32_t st = sbase + (uint32_t)(i % HM_NST) * HM_STAGE;

#pragma unroll
        for (int s = 0; s < 2; s++) {
            uint32_t ah[4][4], al[4][4], bh[4][2], bl[4][2];
#pragma unroll
            for (int t = 0; t < 4; t++) {
                int m = warp_m * 64 + t * 16 + aml;
                uint32_t off = swz(m, 2 * s + acs);
                ldsm4(ah[t], st + off);
                ldsm4(al[t], st + 8192 + off);
            }
#pragma unroll
            for (int p = 0; p < 2; p++) {
                int n = warp_n * 32 + p * 16 + bnl;
                uint32_t off = swz(n, 2 * s + bcs);
                uint32_t r[4];
                ldsm4(r, st + 16384 + off);
                bh[2*p][0] = r[0]; bh[2*p][1] = r[1];
                bh[2*p+1][0] = r[2]; bh[2*p+1][1] = r[3];
                ldsm4(r, st + 24576 + off);
                bl[2*p][0] = r[0]; bl[2*p][1] = r[1];
                bl[2*p+1][0] = r[2]; bl[2*p+1][1] = r[3];
            }
#pragma unroll
            for (int t = 0; t < 4; t++)
#pragma unroll
                for (int j = 0; j < 4; j++) {
                    mma16816(acc[t][j], ah[t], bh[j]);
                    mma16816(acc[t][j], ah[t], bl[j]);
                    mma16816(acc[t][j], al[t], bh[j]);
                }
        }
        __syncthreads();
        if (i + HM_NST < T) { load_stage(i + HM_NST, i % HM_NST); cp_commit(); }
    }

#pragma unroll
    for (int t = 0; t < 4; t++) {
        int m = row0 + warp_m * 64 + t * 16 + (lane >> 2);
#pragma unroll
        for (int j = 0; j < 4; j++) {
            int n = col0 + warp_n * 32 + j * 8 + (lane & 3) * 2;
            if (n >= Nb) continue;
            float v0 = acc[t][j][0], v1 = acc[t][j][1];
            float v2 = acc[t][j][2], v3 = acc[t][j][3];
            if (EPI == 1) {
                float b0 = bias[n], b1 = bias[n + 1];
                v0 += b0; v1 += b1; v2 += b0; v3 += b1;
                v0 = (v0 > 20.f) ? v0 : log1pf(__expf(v0));
                v1 = (v1 > 20.f) ? v1 : log1pf(__expf(v1));
                v2 = (v2 > 20.f) ? v2 : log1pf(__expf(v2));
                v3 = (v3 > 20.f) ? v3 : log1pf(__expf(v3));
            }
            *(float2*)(C + (size_t)m * ldc + n) = make_float2(v0, v1);
            *(float2*)(C + (size_t)(m + 8) * ldc + n) = make_float2(v2, v3);
        }
    }
}

// =============== HMMA GEMM big (128x128 tile, 128 threads, warp 64x64) ============
// 4 warps/CTA, 3 stages x 32KB = 97KB smem -> 2 CTAs/SM; ONE __syncthreads per K-iter.
#define HB_STAGE 32768            // Ahi 8K | Alo 8K | Bhi 8K | Blo 8K
#define HB_NST   3
#define HB_SMEM  (HB_NST * HB_STAGE + 1024)

__global__ __launch_bounds__(128, 2)
void hmma_gemm_b(const __nv_bfloat16* __restrict__ Ahi, const __nv_bfloat16* __restrict__ Alo,
                 const __nv_bfloat16* __restrict__ Bhi, const __nv_bfloat16* __restrict__ Blo,
                 float* __restrict__ C, int M, int Nb, int K, int lda, int ldb, int ldc)
{
    extern __shared__ uint8_t smem_raw[];
    uint8_t* smem = (uint8_t*)(((uintptr_t)smem_raw + 1023) & ~(uintptr_t)1023);
    const uint32_t sbase = (uint32_t)__cvta_generic_to_shared(smem);

    const int tid = threadIdx.x, wid = tid >> 5, lane = tid & 31;
    const int warp_m = wid & 1, warp_n = wid >> 1;       // 2x2 warps, tile 64x64 each
    const int row0 = blockIdx.y * 128, col0 = blockIdx.x * 128;
    const int T = K >> 5;

    // loader: warp w loads subtile w (Ahi,Alo,Bhi,Blo), 32 threads each
    const int t2 = wid;
    const int cc = lane & 3;
    const int rb = lane >> 2;                            // 0..7, row stride 8
    const __nv_bfloat16* gsrc; int roff, ld;
    if      (t2 == 0) { gsrc = Ahi; roff = row0; ld = lda; }
    else if (t2 == 1) { gsrc = Alo; roff = row0; ld = lda; }
    else if (t2 == 2) { gsrc = Bhi; roff = col0; ld = ldb; }
    else              { gsrc = Blo; roff = col0; ld = ldb; }
    const int rowlim = (t2 >= 2) ? Nb : M;
    const uint32_t dsw = (uint32_t)(t2 * 8192) + (uint32_t)rb * 64 +
                         ((uint32_t)(cc ^ ((rb >> 1) & 3)) << 4);
    const uint8_t* gbase = (const uint8_t*)(gsrc + (size_t)(roff + rb) * ld + cc * 8);
    const size_t grs = (size_t)8 * ld * 2;               // 8-row stride in bytes

    auto load_stage = [&](int tile, int stg) {
        const uint8_t* g = gbase + (size_t)tile * 64;
        uint32_t d = sbase + (uint32_t)stg * HB_STAGE + dsw;
#pragma unroll
        for (int j = 0; j < 16; j++) {
            if (roff + rb + j * 8 < rowlim) cpa16s(d + j * 512, g + (size_t)j * grs);
            else                            cpa16z(d + j * 512, g);
        }
    };

    float acc[4][8][4];
#pragma unroll
    for (int i = 0; i < 4; i++)
#pragma unroll
        for (int j = 0; j < 8; j++)
#pragma unroll
            for (int q = 0; q < 4; q++) acc[i][j][q] = 0.f;

    const int aml = lane & 15;
    const int acs = lane >> 4;
    const int bnl = ((lane >> 4) & 1) * 8 + (lane & 7);
    const int bcs = (lane >> 3) & 1;

    // prologue: NST-1 stages in flight
    for (int s = 0; s < HB_NST - 1 && s < T; s++) { load_stage(s, s); cp_commit(); }

    for (int i = 0; i < T; i++) {
        if (i + HB_NST - 1 < T) cp_wait<HB_NST - 2>(); else cp_wait<0>();
        __syncthreads();                                  // single barrier per iter
        // prefetch stage i+NST-1 into ring slot (i-1)%NST (freed: all warps passed sync)
        if (i + HB_NST - 1 < T) { load_stage(i + HB_NST - 1, (i + HB_NST - 1) % HB_NST); cp_commit(); }

        const uint32_t st = sbase + (uint32_t)(i % HB_NST) * HB_STAGE;
#pragma unroll
        for (int s = 0; s < 2; s++) {
            uint32_t ah[4][4], al[4][4], bh[8][2], bl[8][2];
#pragma unroll
            for (int t = 0; t < 4; t++) {
                int m = warp_m * 64 + t * 16 + aml;
                uint32_t off = swz(m, 2 * s + acs);
                ldsm4(ah[t], st + off);
                ldsm4(al[t], st + 8192 + off);
            }
#pragma unroll
            for (int p = 0; p < 4; p++) {
                int n = warp_n * 64 + p * 16 + bnl;
                uint32_t off = swz(n, 2 * s + bcs);
                uint32_t r[4];
                ldsm4(r, st + 16384 + off);
                bh[2*p][0] = r[0]; bh[2*p][1] = r[1];
                bh[2*p+1][0] = r[2]; bh[2*p+1][1] = r[3];
                ldsm4(r, st + 24576 + off);
                bl[2*p][0] = r[0]; bl[2*p][1] = r[1];
                bl[2*p+1][0] = r[2]; bl[2*p+1][1] = r[3];
            }
#pragma unroll
            for (int t = 0; t < 4; t++)
#pragma unroll
                for (int j = 0; j < 8; j++) {
                    mma16816(acc[t][j], ah[t], bh[j]);
                    mma16816(acc[t][j], ah[t], bl[j]);
                    mma16816(acc[t][j], al[t], bh[j]);
                }
        }
    }

#pragma unroll
    for (int t = 0; t < 4; t++) {
        int m = row0 + warp_m * 64 + t * 16 + (lane >> 2);
#pragma unroll
        for (int j = 0; j < 8; j++) {
            int n = col0 + warp_n * 64 + j * 8 + (lane & 3) * 2;
            if (n >= Nb) continue;
            *(float2*)(C + (size_t)m * ldc + n) = make_float2(acc[t][j][0], acc[t][j][1]);
            *(float2*)(C + (size_t)(m + 8) * ldc + n) = make_float2(acc[t][j][2], acc[t][j][3]);
        }
    }
}

// ---------------- fp32 -> bf16 hi/lo splits (3 kernels so in_proj GEMM = launch idx 3) --
__device__ __forceinline__ void split1(const float* s, __nv_bfloat16* hi, __nv_bfloat16* lo, int i) {
    float v = s[i];
    __nv_bfloat16 h = __float2bfloat16(v);
    hi[i] = h;
    lo[i] = __float2bfloat16(v - __bfloat162float(h));
}

__global__ void split_x_kernel(const float* __restrict__ x, __nv_bfloat16* __restrict__ xhi,
                               __nv_bfloat16* __restrict__ xlo)
{
    int i = blockIdx.x * blockDim.x + threadIdx.x;
    if (i < MTOT * DMODEL) split1(x, xhi, xlo, i);
}

__global__ void split_win_kernel(const float* __restrict__ w, __nv_bfloat16* __restrict__ whi,
                                 __nv_bfloat16* __restrict__ wlo)
{
    int i = blockIdx.x * blockDim.x + threadIdx.x;
    if (i < 2 * DIN * DMODEL) split1(w, whi, wlo, i);
}

__global__ void split_wrest_kernel(const float* __restrict__ wxp, __nv_bfloat16* __restrict__ xph,
                                   __nv_bfloat16* __restrict__ xpl,
                                   const float* __restrict__ wdt, __nv_bfloat16* __restrict__ dth,
                                   __nv_bfloat16* __restrict__ dtl,
                                   const float* __restrict__ wo, __nv_bfloat16* __restrict__ woh,
                                   __nv_bfloat16* __restrict__ wol)
{
    const int n1 = NXP * DIN, n2 = DIN * DTRANK, n3 = DMODEL * DIN;
    int i = blockIdx.x * blockDim.x + threadIdx.x;
    if (i < n1) split1(wxp, xph, xpl, i);
    else if (i < n1 + n2) split1(wdt, dth, dtl, i - n1);
    else if (i < n1 + n2 + n3) split1(wo, woh, wol, i - n1 - n2);
}

// ---------------- split-K reduce (4 partials) + bf16 hi/lo emit ----------------
__global__ void reduce4_emit(const float* __restrict__ part, float* __restrict__ o,
                             __nv_bfloat16* __restrict__ ohi, __nv_bfloat16* __restrict__ olo,
                             int n)
{
    int i = blockIdx.x * blockDim.x + threadIdx.x;
    if (i < n) {
        float s = part[i] + part[(size_t)n + i] + part[2ull * n + i] + part[3ull * n + i];
        o[i] = s;
        __nv_bfloat16 h = __float2bfloat16(s);
        ohi[i] = h;
        olo[i] = __float2bfloat16(s - __bfloat162float(h));
    }
}

// ---------------- depthwise causal conv(4) + bias + SiLU (emits bf16 hi/lo only) ------
__global__ __launch_bounds__(256)
void conv_silu_kernel(const float* __restrict__ xz, const float* __restrict__ cw,
                      const float* __restrict__ cb,
                      __nv_bfloat16* __restrict__ uchi, __nv_bfloat16* __restrict__ uclo)
{
    int idx = blockIdx.x * blockDim.x + threadIdx.x;
    if (idx >= MTOT * DIN / 4) return;
    const int d4  = idx & (DIN / 4 - 1);
    const int row = idx >> 9;
    const int t   = row & (LSEQ - 1);
    const int d   = d4 * 4;
    const int rs  = 2 * DIN;

    const float4* base = (const float4*)(xz + (size_t)row * rs + d);
    float4 x0 = base[0];
    float4 xm1 = (t >= 1) ? *(const float4*)((const float*)base - rs)     : make_float4(0,0,0,0);
    float4 xm2 = (t >= 2) ? *(const float4*)((const float*)base - 2 * rs) : make_float4(0,0,0,0);
    float4 xm3 = (t >= 3) ? *(const float4*)((const float*)base - 3 * rs) : make_float4(0,0,0,0);

    const float4* cw4 = (const float4*)(cw + d * 4);
    float4 w0 = cw4[0], w1 = cw4[1], w2 = cw4[2], w3 = cw4[3];
    float4 bb = *(const float4*)(cb + d);

    float4 a;
    a.x = bb.x + w0.x * xm3.x + w0.y * xm2.x + w0.z * xm1.x + w0.w * x0.x;
    a.y = bb.y + w1.x * xm3.y + w1.y * xm2.y + w1.z * xm1.y + w1.w * x0.y;
    a.z = bb.z + w2.x * xm3.z + w2.y * xm2.z + w2.z * xm1.z + w2.w * x0.z;
    a.w = bb.w + w3.x * xm3.w + w3.y * xm2.w + w3.z * xm1.w + w3.w * x0.w;

    a.x = a.x / (1.f + __expf(-a.x));
    a.y = a.y / (1.f + __expf(-a.y));
    a.z = a.z / (1.f + __expf(-a.z));
    a.w = a.w / (1.f + __expf(-a.w));

    size_t o = (size_t)row * DIN + d;
    __nv_bfloat16 h0 = __float2bfloat16(a.x), h1 = __float2bfloat16(a.y);
    __nv_bfloat16 h2 = __float2bfloat16(a.z), h3 = __float2bfloat16(a.w);
    __nv_bfloat162* ph = (__nv_bfloat162*)(uchi + o);
    ph[0] = __nv_bfloat162(h0, h1); ph[1] = __nv_bfloat162(h2, h3);
    __nv_bfloat162* pl = (__nv_bfloat162*)(uclo + o);
    pl[0] = __nv_bfloat162(__float2bfloat16(a.x - __bfloat162float(h0)),
                           __float2bfloat16(a.y - __bfloat162float(h1)));
    pl[1] = __nv_bfloat162(__float2bfloat16(a.z - __bfloat162float(h2)),
                           __float2bfloat16(a.w - __bfloat162float(h3)));
}

// ---------------- selective scan (u reconstructed from bf16 hi/lo) ----------------
__global__ __launch_bounds__(128)
void scan_kernel(const float* __restrict__ dt,
                 const __nv_bfloat16* __restrict__ uchi, const __nv_bfloat16* __restrict__ uclo,
                 const float* __restrict__ xz, const float* __restrict__ xdbl,
                 const float* __restrict__ A_log, const float* __restrict__ Dp,
                 __nv_bfloat16* __restrict__ yhi, __nv_bfloat16* __restrict__ ylo)
{
    constexpr int CHB = 8, TC = 32;
    __shared__ __align__(16) float s_dt[2][TC][CHB];
    __shared__ __align__(16) __nv_bfloat162 s_uh[2][TC][CHB / 2];
    __shared__ __align__(16) __nv_bfloat162 s_ul[2][TC][CHB / 2];
    __shared__ __align__(16) float s_z [2][TC][CHB];
    __shared__ __align__(16) float s_bc[2][TC][32];
    __shared__ float s_y[TC][CHB];
    __shared__ float s_D[CHB];

    const int tid  = threadIdx.x;
    const int warp = tid >> 5, lane = tid & 31;
    const int n    = lane & 15;
    const int chw  = lane >> 4;
    const int blk  = blockIdx.x;
    const int b     = blk / (DIN / CHB);
    const int dbase = (blk % (DIN / CHB)) * CHB;
    const int cc    = warp * 2 + chw;
    const int d     = dbase + cc;
    const size_t bL0 = (size_t)b * LSEQ;

    const float Acoef = -__expf(A_log[d * DSTATE + n]);
    if (tid < CHB) s_D[tid] = Dp[dbase + tid];
    float h = 0.f;

    auto load_chunk = [&](int c, int buf) {
        int t0 = c * TC;
#pragma unroll
        for (int i = 0; i < 2; i++) {
            int idx = tid + i * 128;
            int t = idx >> 3, ch = idx & 7;
            size_t r = bL0 + t0 + t;
            cpa4(&s_dt[buf][t][ch], dt + r * DIN + dbase + ch);
            cpa4(&s_z [buf][t][ch], xz + r * (2 * DIN) + DIN + dbase + ch);
            if ((ch & 1) == 0) {
                cpa4(&s_uh[buf][t][ch >> 1], uchi + r * DIN + dbase + ch);
                cpa4(&s_ul[buf][t][ch >> 1], uclo + r * DIN + dbase + ch);
            }
        }
#pragma unroll
        for (int i = 0; i < 2; i++) {
            int f = tid + i * 128;
            int t = f >> 3, j = f & 7;
            cpa16(&s_bc[buf][t][j * 4], xdbl + (bL0 + t0 + t) * NXP + DTRANK + j * 4);
        }
    };

    constexpr int NCH = LSEQ / TC;
    load_chunk(0, 0);
    cp_commit();

    for (int c = 0; c < NCH; c++) {
        int buf = c & 1;
        if (c + 1 < NCH) {
            load_chunk(c + 1, buf ^ 1);
            cp_commit();
            cp_wait<1>();
        } else {
            cp_wait<0>();
        }
        __syncthreads();

#pragma unroll 8
        for (int t = 0; t < TC; t++) {
            float dtv = s_dt[buf][t][cc];
            __nv_bfloat162 uh2 = s_uh[buf][t][cc >> 1];
            __nv_bfloat162 ul2 = s_ul[buf][t][cc >> 1];
            float uv = (cc & 1) ? (__bfloat162float(uh2.y) + __bfloat162float(ul2.y))
                                : (__bfloat162float(uh2.x) + __bfloat162float(ul2.x));
            float bv  = s_bc[buf][t][n];
            float cv  = s_bc[buf][t][16 + n];
            float dA  = __expf(dtv * Acoef);
            h = fmaf(h, dA, dtv * uv * bv);
            float p = h * cv;
            p += __shfl_xor_sync(0xffffffffu, p, 1);
            p += __shfl_xor_sync(0xffffffffu, p, 2);
            p += __shfl_xor_sync(0xffffffffu, p, 4);
            p += __shfl_xor_sync(0xffffffffu, p, 8);
            if (n == 0) s_y[t][cc] = p;
        }
        __syncthreads();

        int t0 = c * TC;
#pragma unroll
        for (int i = 0; i < 2; i++) {
            int idx = tid + i * 128;
            int t = idx >> 3, ch = idx & 7;
            float p  = s_y[t][ch];
            __nv_bfloat162 uh2 = s_uh[buf][t][ch >> 1];
            __nv_bfloat162 ul2 = s_ul[buf][t][ch >> 1];
            float uv = (ch & 1) ? (__bfloat162float(uh2.y) + __bfloat162float(ul2.y))
                                : (__bfloat162float(uh2.x) + __bfloat162float(ul2.x));
            float zv = s_z[buf][t][ch];
            float yv = fmaf(s_D[ch], uv, p);
            yv *= zv / (1.f + __expf(-zv));
            __nv_bfloat16 hb = __float2bfloat16(yv);
            size_t o = (bL0 + t0 + t) * DIN + dbase + ch;
            yhi[o] = hb;
            ylo[o] = __float2bfloat16(yv - __bfloat162float(hb));
        }
    }
}

// ---------------- residual + LayerNorm ----------------
__global__ __launch_bounds__(128)
void ln_kernel(const float* __restrict__ mo, const float* __restrict__ x,
               const float* __restrict__ w, const float* __restrict__ bb,
               float* __restrict__ out)
{
    const int row = blockIdx.x, tid = threadIdx.x;
    const float4* m4 = (const float4*)(mo + (size_t)row * DMODEL);
    const float4* x4 = (const float4*)(x  + (size_t)row * DMODEL);

    float4 a0 = m4[tid],       c0 = x4[tid];
    float4 a1 = m4[tid + 128], c1 = x4[tid + 128];
    float4 v0 = make_float4(a0.x + c0.x, a0.y + c0.y, a0.z + c0.z, a0.w + c0.w);
    float4 v1 = make_float4(a1.x + c1.x, a1.y + c1.y, a1.z + c1.z, a1.w + c1.w);

    float s  = v0.x + v0.y + v0.z + v0.w + v1.x + v1.y + v1.z + v1.w;
    float ss = v0.x * v0.x + v0.y * v0.y + v0.z * v0.z + v0.w * v0.w
             + v1.x * v1.x + v1.y * v1.y + v1.z * v1.z + v1.w * v1.w;
#pragma unroll
    for (int m = 16; m; m >>= 1) {
        s  += __shfl_xor_sync(0xffffffffu, s,  m);
        ss += __shfl_xor_sync(0xffffffffu, ss, m);
    }
    __shared__ float rs[4], rss[4];
    if ((tid & 31) == 0) { rs[tid >> 5] = s; rss[tid >> 5] = ss; }
    __syncthreads();
    s  = rs[0]  + rs[1]  + rs[2]  + rs[3];
    ss = rss[0] + rss[1] + rss[2] + rss[3];

    const float mu   = s * (1.f / DMODEL);
    const float var  = ss * (1.f / DMODEL) - mu * mu;
    const float rstd = rsqrtf(var + 1e-5f);

    const float4* w4 = (const float4*)w;
    const float4* b4 = (const float4*)bb;
    float4* o4 = (float4*)(out + (size_t)row * DMODEL);

    float4 ww = w4[tid], bv = b4[tid];
    o4[tid] = make_float4((v0.x - mu) * rstd * ww.x + bv.x,
                          (v0.y - mu) * rstd * ww.y + bv.y,
                          (v0.z - mu) * rstd * ww.z + bv.z,
                          (v0.w - mu) * rstd * ww.w + bv.w);
    ww = w4[tid + 128]; bv = b4[tid + 128];
    o4[tid + 128] = make_float4((v1.x - mu) * rstd * ww.x + bv.x,
                                (v1.y - mu) * rstd * ww.y + bv.y,
                                (v1.z - mu) * rstd * ww.z + bv.z,
                                (v1.w - mu) * rstd * ww.w + bv.w);
}

// ---------------- launch ----------------
extern "C" void kernel_launch(void* const* d_in, const int* in_sizes, int n_in,
                              void* d_out, int out_size)
{
    const float* x      = (const float*)d_in[0];
    const float* w_in   = (const float*)d_in[1];
    const float* conv_w = (const float*)d_in[2];
    const float* conv_b = (const float*)d_in[3];
    const float* w_xp   = (const float*)d_in[4];
    const float* w_dt   = (const float*)d_in[5];
    const float* b_dt   = (const float*)d_in[6];
    const float* A_log  = (const float*)d_in[7];
    const float* Dvec   = (const float*)d_in[8];
    const float* w_out  = (const float*)d_in[9];
    const float* ln_w   = (const float*)d_in[10];
    const float* ln_b   = (const float*)d_in[11];
    float* out = (float*)d_out;

    float *p_xz, *p_xdp, *p_xd, *p_dt, *p_mo;
    __nv_bfloat16 *p_xhi, *p_xlo, *p_wihi, *p_wilo, *p_wohi, *p_wolo, *p_yhi, *p_ylo;
    __nv_bfloat16 *p_uchi, *p_uclo, *p_xdhi, *p_xdlo, *p_wxph, *p_wxpl, *p_wdth, *p_wdtl;
    cudaGetSymbolAddress((void**)&p_xz,  g_xz);
    cudaGetSymbolAddress((void**)&p_xdp, g_xdbl_part);
    cudaGetSymbolAddress((void**)&p_xd,  g_xdbl);
    cudaGetSymbolAddress((void**)&p_dt,  g_dt);
    cudaGetSymbolAddress((void**)&p_mo,  g_mo);
    cudaGetSymbolAddress((void**)&p_xhi, g_xhi);
    cudaGetSymbolAddress((void**)&p_xlo, g_xlo);
    cudaGetSymbolAddress((void**)&p_wihi, g_wihi);
    cudaGetSymbolAddress((void**)&p_wilo, g_wilo);
    cudaGetSymbolAddress((void**)&p_wohi, g_wohi);
    cudaGetSymbolAddress((void**)&p_wolo, g_wolo);
    cudaGetSymbolAddress((void**)&p_yhi, g_yhi);
    cudaGetSymbolAddress((void**)&p_ylo, g_ylo);
    cudaGetSymbolAddress((void**)&p_uchi, g_uchi);
    cudaGetSymbolAddress((void**)&p_uclo, g_uclo);
    cudaGetSymbolAddress((void**)&p_xdhi, g_xdhi);
    cudaGetSymbolAddress((void**)&p_xdlo, g_xdlo);
    cudaGetSymbolAddress((void**)&p_wxph, g_wxphi);
    cudaGetSymbolAddress((void**)&p_wxpl, g_wxplo);
    cudaGetSymbolAddress((void**)&p_wdth, g_wdthi);
    cudaGetSymbolAddress((void**)&p_wdtl, g_wdtlo);

    cudaFuncSetAttribute(hmma_gemm<0>, cudaFuncAttributeMaxDynamicSharedMemorySize, HM_SMEM);
    cudaFuncSetAttribute(hmma_gemm<1>, cudaFuncAttributeMaxDynamicSharedMemorySize, HM_SMEM);
    cudaFuncSetAttribute(hmma_gemm_b, cudaFuncAttributeMaxDynamicSharedMemorySize, HB_SMEM);

    // [0..2] splits (3 launches so the in_proj GEMM is launch index 3 = profiled slot)
    split_x_kernel<<<(MTOT * DMODEL + 255) / 256, 256>>>(x, p_xhi, p_xlo);
    split_win_kernel<<<(2 * DIN * DMODEL + 255) / 256, 256>>>(w_in, p_wihi, p_wilo);
    {
        int nW = NXP * DIN + DIN * DTRANK + DMODEL * DIN;
        split_wrest_kernel<<<(nW + 255) / 256, 256>>>(w_xp, p_wxph, p_wxpl,
                                                      w_dt, p_wdth, p_wdtl,
                                                      w_out, p_wohi, p_wolo);
    }

    // [3] xz = x @ in_proj_w^T   (4096 x 4096, K=1024) -- big HMMA  << PROFILED >>
    hmma_gemm_b<<<dim3(32, 32), 128, HB_SMEM>>>(p_xhi, p_xlo, p_wihi, p_wilo, p_xz,
                                                MTOT, 2 * DIN, DMODEL,
                                                DMODEL, DMODEL, 2 * DIN);

    // [4] depthwise causal conv + bias + silu -> u_c (bf16 hi/lo only)
    conv_silu_kernel<<<(MTOT * DIN / 4 + 255) / 256, 256>>>(p_xz, conv_w, conv_b,
                                                            p_uchi, p_uclo);

    // [5] x_dbl = u_c @ x_proj_w^T  (4096 x 96, K=2048), HMMA split-K 4 + reduce
    hmma_gemm<0><<<dim3(1, 32, 4), 256, HM_SMEM>>>(p_uchi, p_uclo, p_wxph, p_wxpl, p_xdp,
                                                   nullptr, MTOT, NXP, DIN,
                                                   DIN, DIN, NXP);
    // [6]
    reduce4_emit<<<(MTOT * NXP + 255) / 256, 256>>>(p_xdp, p_xd, p_xdhi, p_xdlo, MTOT * NXP);

    // [7] dt = softplus(x_dbl[:, :64] @ dt_proj_w^T + b)  (4096 x 2048, K=64)
    hmma_gemm<1><<<dim3(16, 32, 1), 256, HM_SMEM>>>(p_xdhi, p_xdlo, p_wdth, p_wdtl, p_dt,
                                                    b_dt, MTOT, DIN, DTRANK,
                                                    NXP, DTRANK, DIN);

    // [8] selective scan (+ D*u, * silu(z)) -> y (bf16 hi/lo)
    scan_kernel<<<BSZ * DIN / 8, 128>>>(p_dt, p_uchi, p_uclo, p_xz, p_xd, A_log, Dvec,
                                        p_yhi, p_ylo);

    // [9] mo = y @ out_proj_w^T  (4096 x 1024, K=2048) -- big HMMA
    hmma_gemm_b<<<dim3(8, 32), 128, HB_SMEM>>>(p_yhi, p_ylo, p_wohi, p_wolo, p_mo,
                                               MTOT, DMODEL, DIN,
                                               DIN, DIN, DMODEL);

    // [10] out = LayerNorm(mo + x)
    ln_kernel<<<MTOT, 128>>>(p_mo, x, ln_w, ln_b, out);
}